// round 1
// baseline (speedup 1.0000x reference)
#include <cuda_runtime.h>
#include <cuda_bf16.h>
#include <cstdint>

#define B 512
#define HID 128
#define IN_DIM 595
#define TJ 64

// ---------------- device scratch (no allocations allowed) ----------------
__device__ float g_scratch[4 * B * HID]; // H1, H2, U, V

// ---------------- packed f32x2 helpers ----------------
__device__ __forceinline__ unsigned long long pk2(float x) {
    unsigned long long r;
    asm("mov.b64 %0, {%1, %2};" : "=l"(r) : "r"(__float_as_uint(x)), "r"(__float_as_uint(x)));
    return r;
}
__device__ __forceinline__ unsigned long long fma2(unsigned long long a, unsigned long long b, unsigned long long c) {
    unsigned long long d;
    asm("fma.rn.f32x2 %0, %1, %2, %3;" : "=l"(d) : "l"(a), "l"(b), "l"(c));
    return d;
}
__device__ __forceinline__ void unpk2(unsigned long long v, float& lo, float& hi) {
    unsigned int a, b;
    asm("mov.b64 {%0, %1}, %2;" : "=r"(a), "=r"(b) : "l"(v));
    lo = __uint_as_float(a);
    hi = __uint_as_float(b);
}

// ---------------- small GEMM: Y[m,n] = act(X[m,:K] @ W[K,N] + bias) ----------------
// One block per row m, blockDim = N = 128. W row-major [K, N].
__global__ void row_gemm(const float* __restrict__ X, const float* __restrict__ W,
                         const float* __restrict__ bias, float* __restrict__ Y,
                         int K, int hasBias, int doRelu) {
    __shared__ float xs[608];
    const int m = blockIdx.x;
    const int n = threadIdx.x;
    for (int k = threadIdx.x; k < K; k += blockDim.x) xs[k] = X[m * K + k];
    __syncthreads();
    float acc = hasBias ? bias[n] : 0.0f;
    const float* Wn = W + n;
#pragma unroll 4
    for (int k = 0; k < K; ++k) acc = fmaf(xs[k], Wn[k * HID], acc);
    if (doRelu) acc = fmaxf(acc, 0.0f);
    Y[m * HID + n] = acc;
}

// ---------------- main pairwise kernel ----------------
// Block (i, jt): scores[i, jt*64 .. +63].
// pre[j,k] = sum_d |H[i,d]-H[j,d]| * C[d,k] + U[i,k] + V[j,k]   (bp1 folded in U)
// score[i,j] = sum_k relu(pre[j,k]) * Wp2[k] + bp2
__global__ __launch_bounds__(256, 2) void pair_kernel(
    const float* __restrict__ H, const float* __restrict__ Wp1,
    const float* __restrict__ U, const float* __restrict__ V,
    const float* __restrict__ Wp2, const float* __restrict__ bp2,
    float* __restrict__ out) {
    extern __shared__ float sm[];
    float* Cs  = sm;            // [128][128] = 16384
    float* Ds  = sm + 16384;    // [128 d][64 j] = 8192
    float* his = sm + 24576;    // 128
    float* Us  = sm + 24704;    // 128
    float* w2s = sm + 24832;    // 128

    const int tid = threadIdx.x;
    const int i   = blockIdx.x;
    const int j0  = blockIdx.y * TJ;

    // stage C = Wp1 rows [256..383]
    {
        const float4* Cg  = (const float4*)(Wp1 + 256 * HID);
        float4*       Cs4 = (float4*)Cs;
#pragma unroll
        for (int t = 0; t < 16; ++t) Cs4[tid + t * 256] = Cg[tid + t * 256];
    }
    if (tid < 128) {
        his[tid] = H[i * HID + tid];
        Us[tid]  = U[i * HID + tid];
        w2s[tid] = Wp2[tid];
    }
    __syncthreads();

    // build D[d][j] = |H[j0+j][d] - his[d]|  (writes conflict-free: j = lane)
    {
        const int j    = tid & 63;
        const int dblk = (tid >> 6) * 32;
        const float4* Hj = (const float4*)(H + (j0 + j) * HID + dblk);
#pragma unroll
        for (int it = 0; it < 8; ++it) {
            float4 v = Hj[it];
            int d = dblk + it * 4;
            Ds[(d + 0) * TJ + j] = fabsf(v.x - his[d + 0]);
            Ds[(d + 1) * TJ + j] = fabsf(v.y - his[d + 1]);
            Ds[(d + 2) * TJ + j] = fabsf(v.z - his[d + 2]);
            Ds[(d + 3) * TJ + j] = fabsf(v.w - his[d + 3]);
        }
    }
    __syncthreads();

    // 64x128x128 GEMM, thread tile 4(j) x 8(k), packed f32x2 along k
    const int ty = tid >> 4, tx = tid & 15;
    const int jf = ty * 4, kf = tx * 8;
    unsigned long long acc[4][4];
#pragma unroll
    for (int a = 0; a < 4; ++a)
#pragma unroll
        for (int b = 0; b < 4; ++b) acc[a][b] = 0ull;

    const unsigned long long* Cs64 = (const unsigned long long*)Cs;
#pragma unroll 2
    for (int d = 0; d < 128; ++d) {
        float4 a4 = *(const float4*)(Ds + d * TJ + jf);
        ulonglong2 b01 = *(const ulonglong2*)(Cs64 + d * 64 + tx * 4);
        ulonglong2 b23 = *(const ulonglong2*)(Cs64 + d * 64 + tx * 4 + 2);
        unsigned long long av0 = pk2(a4.x), av1 = pk2(a4.y), av2 = pk2(a4.z), av3 = pk2(a4.w);
        unsigned long long bv[4] = {b01.x, b01.y, b23.x, b23.y};
#pragma unroll
        for (int p = 0; p < 4; ++p) {
            acc[0][p] = fma2(av0, bv[p], acc[0][p]);
            acc[1][p] = fma2(av1, bv[p], acc[1][p]);
            acc[2][p] = fma2(av2, bv[p], acc[2][p]);
            acc[3][p] = fma2(av3, bv[p], acc[3][p]);
        }
    }

    // epilogue: +U_i +V_j, relu, dot Wp2, reduce across the 16 k-threads
    const float b2v = bp2[0];
#pragma unroll
    for (int jj = 0; jj < 4; ++jj) {
        const int j = j0 + jf + jj;
        const float4* Vj = (const float4*)(V + j * HID + kf);
        float4 v0 = Vj[0], v1 = Vj[1];
        float vr[8] = {v0.x, v0.y, v0.z, v0.w, v1.x, v1.y, v1.z, v1.w};
        float partial = 0.0f;
#pragma unroll
        for (int p = 0; p < 4; ++p) {
            float lo, hi;
            unpk2(acc[jj][p], lo, hi);
            int k = kf + 2 * p;
            float pre0 = lo + Us[k]     + vr[2 * p];
            float pre1 = hi + Us[k + 1] + vr[2 * p + 1];
            partial = fmaf(fmaxf(pre0, 0.0f), w2s[k],     partial);
            partial = fmaf(fmaxf(pre1, 0.0f), w2s[k + 1], partial);
        }
#pragma unroll
        for (int off = 8; off > 0; off >>= 1)
            partial += __shfl_down_sync(0xffffffffu, partial, off, 16);
        if (tx == 0) out[i * B + j] = partial + b2v;
    }
}

// ---------------- launch ----------------
extern "C" void kernel_launch(void* const* d_in, const int* in_sizes, int n_in,
                              void* d_out, int out_size) {
    const float* x   = (const float*)d_in[0];
    const float* W1  = (const float*)d_in[1];
    const float* b1  = (const float*)d_in[2];
    const float* W2  = (const float*)d_in[3];
    const float* b2  = (const float*)d_in[4];
    const float* Wp1 = (const float*)d_in[5];
    const float* bp1 = (const float*)d_in[6];
    const float* Wp2 = (const float*)d_in[7];
    const float* bp2 = (const float*)d_in[8];
    float* out = (float*)d_out;

    float* sp = nullptr;
    cudaGetSymbolAddress((void**)&sp, g_scratch);
    float* H1 = sp;
    float* H2 = sp + B * HID;
    float* U  = sp + 2 * B * HID;
    float* V  = sp + 3 * B * HID;

    // encoder
    row_gemm<<<B, HID>>>(x,  W1, b1, H1, IN_DIM, 1, 1);
    row_gemm<<<B, HID>>>(H1, W2, b2, H2, HID,    1, 1);
    // U = H@A + bp1 ; V = H@B
    row_gemm<<<B, HID>>>(H2, Wp1,             bp1,     U, HID, 1, 0);
    row_gemm<<<B, HID>>>(H2, Wp1 + HID * HID, nullptr, V, HID, 0, 0);

    // pairwise
    const int smem = (24832 + 128) * sizeof(float); // 99840 B
    cudaFuncSetAttribute(pair_kernel, cudaFuncAttributeMaxDynamicSharedMemorySize, smem);
    dim3 grid(B, B / TJ);
    pair_kernel<<<grid, 256, smem>>>(H2, Wp1, U, V, Wp2, bp2, out);
}

// round 4
// speedup vs baseline: 2.6752x; 2.6752x over previous
#include <cuda_runtime.h>
#include <cuda_bf16.h>
#include <cstdint>

#define B 512
#define HID 128
#define IN_DIM 595

#define TSTR 272            // staged tile row stride (bytes) -> conflict-free ldmatrix
#define TILE_BYTES 34816    // 128 rows * 272

// ---------------- device scratch (no allocations allowed) ----------------
__device__ float g_scratch[4 * B * HID];               // H1, H2, U, V
__device__ __align__(16) unsigned char g_bsw[69632];   // C^T staged: hi[34816], lo[34816]

// ======================= helpers =======================
__device__ __forceinline__ uint32_t smem_u32(const void* p) {
    uint32_t a;
    asm("{ .reg .u64 t; cvta.to.shared.u64 t, %1; cvt.u32.u64 %0, t; }" : "=r"(a) : "l"(p));
    return a;
}
// pack two fp32 -> bf16x2 (lo half = first arg)
__device__ __forceinline__ uint32_t bf2(float lo, float hi) {
    uint32_t r;
    asm("cvt.rn.bf16x2.f32 %0, %1, %2;" : "=r"(r) : "f"(hi), "f"(lo));
    return r;
}
__device__ __forceinline__ void ldm4(uint32_t* r, uint32_t addr) {
    asm volatile("ldmatrix.sync.aligned.m8n8.x4.shared.b16 {%0,%1,%2,%3}, [%4];"
                 : "=r"(r[0]), "=r"(r[1]), "=r"(r[2]), "=r"(r[3]) : "r"(addr));
}
__device__ __forceinline__ void mma_bf16(float* c, const uint32_t* a, uint32_t b0, uint32_t b1) {
    asm volatile(
        "mma.sync.aligned.m16n8k16.row.col.f32.bf16.bf16.f32 "
        "{%0,%1,%2,%3}, {%4,%5,%6,%7}, {%8,%9}, {%0,%1,%2,%3};"
        : "+f"(c[0]), "+f"(c[1]), "+f"(c[2]), "+f"(c[3])
        : "r"(a[0]), "r"(a[1]), "r"(a[2]), "r"(a[3]), "r"(b0), "r"(b1));
}

// ======================= encoder GEMM =======================
// Y[m,n] = act(X[m,:K] @ W[K,128] + bias). 4 rows/block, 512 threads, K split 4 ways.
__global__ __launch_bounds__(512) void enc_gemm(const float* __restrict__ X,
                                                const float* __restrict__ W,
                                                const float* __restrict__ bias,
                                                float* __restrict__ Y, int K, int doRelu) {
    __shared__ float Xs[4 * 608];
    __shared__ float red[3][4][128];
    const int tid = threadIdx.x;
    const int n = tid & 127, q = tid >> 7;
    const int m0 = blockIdx.x * 4;
    for (int idx = tid; idx < 4 * K; idx += 512) {
        int r = idx / K, k = idx - r * K;
        Xs[r * 608 + k] = X[(m0 + r) * K + k];
    }
    __syncthreads();
    const int kb = (K * q) >> 2, ke = (K * (q + 1)) >> 2;
    float a0 = 0.f, a1 = 0.f, a2 = 0.f, a3 = 0.f;
    const float* Wn = W + n;
    for (int k = kb; k < ke; ++k) {
        float w = __ldg(Wn + k * 128);
        a0 = fmaf(Xs[k], w, a0);
        a1 = fmaf(Xs[608 + k], w, a1);
        a2 = fmaf(Xs[1216 + k], w, a2);
        a3 = fmaf(Xs[1824 + k], w, a3);
    }
    if (q) {
        red[q - 1][0][n] = a0; red[q - 1][1][n] = a1;
        red[q - 1][2][n] = a2; red[q - 1][3][n] = a3;
    }
    __syncthreads();
    if (q == 0) {
        float bv = bias ? bias[n] : 0.f;
        float r0 = a0 + red[0][0][n] + red[1][0][n] + red[2][0][n] + bv;
        float r1 = a1 + red[0][1][n] + red[1][1][n] + red[2][1][n] + bv;
        float r2 = a2 + red[0][2][n] + red[1][2][n] + red[2][2][n] + bv;
        float r3 = a3 + red[0][3][n] + red[1][3][n] + red[2][3][n] + bv;
        if (doRelu) {
            r0 = fmaxf(r0, 0.f); r1 = fmaxf(r1, 0.f);
            r2 = fmaxf(r2, 0.f); r3 = fmaxf(r3, 0.f);
        }
        Y[(m0 + 0) * 128 + n] = r0;
        Y[(m0 + 1) * 128 + n] = r1;
        Y[(m0 + 2) * 128 + n] = r2;
        Y[(m0 + 3) * 128 + n] = r3;
    }
}

// ======================= prep: C^T hi/lo split, staged layout =======================
// Bt[k][d] = C[d][k] = Wp1[(256+d)*128 + k], row stride TSTR bytes.
__global__ void prep_C(const float* __restrict__ Wp1) {
    int idx = blockIdx.x * 256 + threadIdx.x;   // 16384 total
    int k = idx >> 7, d = idx & 127;
    float v = Wp1[(256 + d) * 128 + k];
    __nv_bfloat16 h = __float2bfloat16_rn(v);
    float lo = v - __bfloat162float(h);
    __nv_bfloat16 l = __float2bfloat16_rn(lo);
    uint32_t off = (uint32_t)k * TSTR + d * 2;
    *(__nv_bfloat16*)(g_bsw + off) = h;
    *(__nv_bfloat16*)(g_bsw + TILE_BYTES + off) = l;
}

// ======================= pairwise kernel (mma.sync bf16) =======================
// grid (256, 4): blockIdx.x -> i-pair, blockIdx.y -> 128-wide j tile.
// D[j,k] = sum_d |h_i[d]-h_j[d]| * C[d,k] via 3-term hi/lo bf16 MMA;
// score = relu(D + U_i + V_j) . Wp2 + bp2.
#define OFF_B   139264          // 2 A-tiles (hi+lo each) before this
#define OFF_HIS 208896
#define OFF_US  209920
#define OFF_W2  210944
#define OFF_RED 211456
#define SMEM_PAIR 213504

__global__ __launch_bounds__(256, 1) void pair_mma(
    const float* __restrict__ H, const float* __restrict__ U, const float* __restrict__ V,
    const float* __restrict__ Wp2, const float* __restrict__ bp2, float* __restrict__ out) {
    extern __shared__ char sm[];
    const uint32_t sb = smem_u32(sm);
    float* his = (float*)(sm + OFF_HIS);   // [2][128]
    float* Us  = (float*)(sm + OFF_US);    // [2][128]
    float* w2  = (float*)(sm + OFF_W2);    // [128]
    float* red = (float*)(sm + OFF_RED);   // [4][128]

    const int tid  = threadIdx.x;
    const int lane = tid & 31, wid = tid >> 5;
    const int wm = wid & 1, wn = wid >> 1;     // warp tile: 64 j-rows x 32 k-cols
    const int i0 = blockIdx.x * 2;
    const int j0 = blockIdx.y * 128;

    // stage pre-split B (C^T hi+lo, 69632 B, linear copy)
    {
        const uint4* g = (const uint4*)g_bsw;
        uint4* s = (uint4*)(sm + OFF_B);
#pragma unroll
        for (int t = 0; t < 17; ++t) s[tid + t * 256] = g[tid + t * 256];
    }
    if (tid < 128) {
        his[tid]       = H[i0 * HID + tid];
        his[128 + tid] = H[(i0 + 1) * HID + tid];
        Us[tid]        = U[i0 * HID + tid];
        Us[128 + tid]  = U[(i0 + 1) * HID + tid];
        w2[tid]        = Wp2[tid];
    }
    __syncthreads();

    // build A tiles: A[j][d] = |h_i[d]-h_{j0+j}[d]|, hi/lo split, for both i.
    {
        const int j  = tid >> 1;
        const int dh = (tid & 1) << 6;
        const float4* Hj = (const float4*)(H + (size_t)(j0 + j) * HID + dh);
        const uint32_t offr = (uint32_t)j * TSTR + dh * 2;
#pragma unroll
        for (int t = 0; t < 16; ++t) {
            float4 v = Hj[t];
            const int d = dh + t * 4;
            const uint32_t off = offr + t * 8;
#pragma unroll
            for (int ii = 0; ii < 2; ++ii) {
                const float* hh = his + ii * 128;
                float x0 = fabsf(v.x - hh[d]);
                float x1 = fabsf(v.y - hh[d + 1]);
                float x2 = fabsf(v.z - hh[d + 2]);
                float x3 = fabsf(v.w - hh[d + 3]);
                uint32_t h01 = bf2(x0, x1), h23 = bf2(x2, x3);
                float l0 = x0 - __uint_as_float(h01 << 16);
                float l1 = x1 - __uint_as_float(h01 & 0xffff0000u);
                float l2 = x2 - __uint_as_float(h23 << 16);
                float l3 = x3 - __uint_as_float(h23 & 0xffff0000u);
                uint32_t q01 = bf2(l0, l1), q23 = bf2(l2, l3);
                char* abase = sm + ii * (2 * TILE_BYTES);
                *(uint2*)(abase + off)              = make_uint2(h01, h23);
                *(uint2*)(abase + TILE_BYTES + off) = make_uint2(q01, q23);
            }
        }
    }
    __syncthreads();

    // ldmatrix lane addressing (x4: 16 rows, 2 col-halves)
    const uint32_t aRowOff = (uint32_t)(wm * 64 + (lane & 15)) * TSTR + (lane >> 4) * 16;
    const uint32_t bAddrBase = sb + OFF_B + (uint32_t)(wn * 32 + (lane & 15)) * TSTR + (lane >> 4) * 16;
    const float b2v = bp2[0];

    for (int ii = 0; ii < 2; ++ii) {
        const uint32_t aAddrBase = sb + ii * (2 * TILE_BYTES) + aRowOff;
        float acc[4][4][4];
#pragma unroll
        for (int a = 0; a < 4; ++a)
#pragma unroll
            for (int b = 0; b < 4; ++b) {
                acc[a][b][0] = 0.f; acc[a][b][1] = 0.f;
                acc[a][b][2] = 0.f; acc[a][b][3] = 0.f;
            }

#pragma unroll
        for (int ks = 0; ks < 8; ++ks) {
            uint32_t ah[4][4], al[4][4], bh[2][4], bl[2][4];
#pragma unroll
            for (int mt = 0; mt < 4; ++mt) {
                ldm4(ah[mt], aAddrBase + mt * (16 * TSTR) + ks * 32);
                ldm4(al[mt], aAddrBase + TILE_BYTES + mt * (16 * TSTR) + ks * 32);
            }
#pragma unroll
            for (int p = 0; p < 2; ++p) {
                ldm4(bh[p], bAddrBase + p * (16 * TSTR) + ks * 32);
                ldm4(bl[p], bAddrBase + TILE_BYTES + p * (16 * TSTR) + ks * 32);
            }
#pragma unroll
            for (int mt = 0; mt < 4; ++mt)
#pragma unroll
                for (int nt = 0; nt < 4; ++nt) {
                    uint32_t b0h = bh[nt >> 1][nt & 1], b1h = bh[nt >> 1][(nt & 1) + 2];
                    uint32_t b0l = bl[nt >> 1][nt & 1], b1l = bl[nt >> 1][(nt & 1) + 2];
                    mma_bf16(acc[mt][nt], ah[mt], b0h, b1h);
                    mma_bf16(acc[mt][nt], ah[mt], b0l, b1l);
                    mma_bf16(acc[mt][nt], al[mt], b0h, b1h);
                }
        }

        // epilogue: relu(acc + U_i + V_j) . w2, reduce over k
        const int kb = wn * 32;
#pragma unroll
        for (int mt = 0; mt < 4; ++mt) {
            const int r0 = wm * 64 + mt * 16 + (lane >> 2);
            float p0 = 0.f, p1 = 0.f;
#pragma unroll
            for (int nt = 0; nt < 4; ++nt) {
                const int k = kb + nt * 8 + (lane & 3) * 2;
                float2 v0 = *(const float2*)(V + (size_t)(j0 + r0) * HID + k);
                float2 v1 = *(const float2*)(V + (size_t)(j0 + r0 + 8) * HID + k);
                float u0 = Us[ii * 128 + k], u1 = Us[ii * 128 + k + 1];
                float w0 = w2[k], w1 = w2[k + 1];
                p0 = fmaf(fmaxf(acc[mt][nt][0] + u0 + v0.x, 0.f), w0, p0);
                p0 = fmaf(fmaxf(acc[mt][nt][1] + u1 + v0.y, 0.f), w1, p0);
                p1 = fmaf(fmaxf(acc[mt][nt][2] + u0 + v1.x, 0.f), w0, p1);
                p1 = fmaf(fmaxf(acc[mt][nt][3] + u1 + v1.y, 0.f), w1, p1);
            }
            p0 += __shfl_down_sync(0xffffffffu, p0, 2, 4);
            p0 += __shfl_down_sync(0xffffffffu, p0, 1, 4);
            p1 += __shfl_down_sync(0xffffffffu, p1, 2, 4);
            p1 += __shfl_down_sync(0xffffffffu, p1, 1, 4);
            if ((lane & 3) == 0) {
                red[wn * 128 + r0]     = p0;
                red[wn * 128 + r0 + 8] = p1;
            }
        }
        __syncthreads();
        if (tid < 128) {
            float s = red[tid] + red[128 + tid] + red[256 + tid] + red[384 + tid] + b2v;
            out[(size_t)(i0 + ii) * B + j0 + tid] = s;
        }
        __syncthreads();
    }
}

// ======================= launch =======================
extern "C" void kernel_launch(void* const* d_in, const int* in_sizes, int n_in,
                              void* d_out, int out_size) {
    const float* x   = (const float*)d_in[0];
    const float* W1  = (const float*)d_in[1];
    const float* b1  = (const float*)d_in[2];
    const float* W2  = (const float*)d_in[3];
    const float* b2  = (const float*)d_in[4];
    const float* Wp1 = (const float*)d_in[5];
    const float* bp1 = (const float*)d_in[6];
    const float* Wp2 = (const float*)d_in[7];
    const float* bp2 = (const float*)d_in[8];
    float* out = (float*)d_out;

    float* sp = nullptr;
    cudaGetSymbolAddress((void**)&sp, g_scratch);
    float* H1 = sp;
    float* H2 = sp + B * HID;
    float* U  = sp + 2 * B * HID;
    float* V  = sp + 3 * B * HID;

    prep_C<<<64, 256>>>(Wp1);
    enc_gemm<<<B / 4, 512>>>(x,  W1, b1, H1, IN_DIM, 1);
    enc_gemm<<<B / 4, 512>>>(H1, W2, b2, H2, HID, 1);
    enc_gemm<<<B / 4, 512>>>(H2, Wp1, bp1, U, HID, 0);
    enc_gemm<<<B / 4, 512>>>(H2, Wp1 + HID * HID, nullptr, V, HID, 0);

    cudaFuncSetAttribute(pair_mma, cudaFuncAttributeMaxDynamicSharedMemorySize, SMEM_PAIR);
    dim3 grid(B / 2, B / 128);
    pair_mma<<<grid, 256, SMEM_PAIR>>>(H2, U, V, Wp2, bp2, out);
}